// round 10
// baseline (speedup 1.0000x reference)
#include <cuda_runtime.h>
#include <cuda_bf16.h>
#include <cstdint>

// MotionPrediction: B=65536, 3 cyclic-MoE layers, dims 256, 4 experts.
// out = sum_e c_e (.) (X @ W_e + b_e), ReLU on layers 1,2.
// R8: int8 IMMA (mma.sync m16n8k32.s8) with fixed-point hi/lo split:
//   v = s*(h + l/256)/127,  v*w = s*sw/16129*(hh + (hl+lh)/256)  [ll dropped]
// Per-row activation scales, per-expert weight scales. Layers emit f32;
// a standalone quant kernel re-splits between layers.

#define BSZ  65536
#define NDIM 256

__device__ float g_H1[BSZ * NDIM];
__device__ float g_H2[BSZ * NDIM];
__device__ float4 g_coeff[BSZ];
__device__ float  g_swe[12];                             // [slot][expert]
__device__ __align__(16) int8_t g_W8hi[3 * 4 * 65536];   // [slot][chunk32][n256][k32]
__device__ __align__(16) int8_t g_W8lo[3 * 4 * 65536];
__device__ __align__(16) int8_t g_A8hi[BSZ * NDIM];
__device__ __align__(16) int8_t g_A8lo[BSZ * NDIM];
__device__ float g_sxA[BSZ];
__device__ __align__(16) int8_t g_B8hi[BSZ * NDIM];
__device__ __align__(16) int8_t g_B8lo[BSZ * NDIM];
__device__ float g_sxB[BSZ];

// ---- SMEM map (bytes) ----
#define ASTR8     272                 // A row: 256 B + 16 pad (conflict-free)
#define SA8_LO    17408               // 64*272
#define SB8_OFF   34816
#define BSTR8     48                  // B row: 32 B + 16 pad
#define SB8_LO    6144                // 128*48
#define SB8_STAGE 12288               // hi+lo
#define SBIAS8    83968               // SB8_OFF + 4*SB8_STAGE
#define SM8_TOTAL 86016

// ---------------------------------------------------------------- helpers
__device__ __forceinline__ uint32_t smem_u32(const void* p) {
    uint32_t a;
    asm("{ .reg .u64 t; cvta.to.shared.u64 t, %1; cvt.u32.u64 %0, t; }"
        : "=r"(a) : "l"(p));
    return a;
}
__device__ __forceinline__ void ldsm4(uint32_t* r, uint32_t a) {
    asm volatile("ldmatrix.sync.aligned.m8n8.x4.shared.b16 {%0,%1,%2,%3}, [%4];"
                 : "=r"(r[0]), "=r"(r[1]), "=r"(r[2]), "=r"(r[3]) : "r"(a));
}
__device__ __forceinline__ void imma16832(int* d, const uint32_t* a,
                                          uint32_t b0, uint32_t b1) {
    asm volatile(
        "mma.sync.aligned.m16n8k32.row.col.s32.s8.s8.s32 "
        "{%0,%1,%2,%3}, {%4,%5,%6,%7}, {%8,%9}, {%0,%1,%2,%3};"
        : "+r"(d[0]), "+r"(d[1]), "+r"(d[2]), "+r"(d[3])
        : "r"(a[0]), "r"(a[1]), "r"(a[2]), "r"(a[3]), "r"(b0), "r"(b1));
}
__device__ __forceinline__ void cpa16(uint32_t s, const void* g) {
    asm volatile("cp.async.cg.shared.global [%0], [%1], 16;" :: "r"(s), "l"(g));
}

// ---------------------------------------------------------------- coeff
__global__ void coeff_kernel(const float* __restrict__ phi) {
    int b = blockIdx.x * blockDim.x + threadIdx.x;
    if (b >= BSZ) return;
    const float TWO_OVER_PI = (float)(2.0 / 3.14159265358979323846);
    float w  = TWO_OVER_PI * phi[b];
    int  wi  = ((int)w) & 3;
    float w2 = w * w, w3 = w2 * w;
    float co[4];
    co[0] = -0.5f * w + w2 - 0.5f * w3;
    co[1] = -2.5f * w2 + 1.5f * w3;
    co[2] =  0.5f * w + 2.0f * w2 - 1.5f * w3;
    co[3] = -0.5f * w2 + 0.5f * w3;
    float c[4];
#pragma unroll
    for (int e = 0; e < 4; ++e) c[e] = co[(e - wi + 5) & 3];
    g_coeff[b] = make_float4(c[0], c[1], c[2], c[3]);
}

// ---------------------------------------------------------------- W quantize
// W [4][256 k][256 n] f32 -> blocked [chunk=e*8+kc][n][k32] int8 hi/lo,
// per-expert scale swe = max|W_e|.
__global__ void convW8_kernel(const float* __restrict__ Wa,
                              const float* __restrict__ Wb,
                              const float* __restrict__ Wc) {
    const int e = blockIdx.x, slot = blockIdx.y;
    const float* W = ((slot == 0) ? Wa : (slot == 1) ? Wb : Wc) + e * 65536;
    const int n = threadIdx.x;
    __shared__ float red[256];
    float m = 0.f;
    for (int k = 0; k < 256; ++k) m = fmaxf(m, fabsf(W[k * 256 + n]));
    red[n] = m;
    __syncthreads();
    for (int s = 128; s > 0; s >>= 1) {
        if (n < s) red[n] = fmaxf(red[n], red[n + s]);
        __syncthreads();
    }
    const float swe = fmaxf(red[0], 1e-30f);
    if (n == 0) g_swe[slot * 4 + e] = swe;
    const float qs = 127.0f / swe;
    uint32_t* hiw = (uint32_t*)(g_W8hi + (size_t)slot * 262144);
    uint32_t* low = (uint32_t*)(g_W8lo + (size_t)slot * 262144);
    uint32_t hb = 0, lb = 0;
    for (int k = 0; k < 256; ++k) {
        float qf = W[k * 256 + n] * qs;
        float h  = rintf(qf);
        float rl = fminf(rintf((qf - h) * 256.0f), 127.0f);
        hb |= ((uint32_t)((int)h  & 255)) << ((k & 3) * 8);
        lb |= ((uint32_t)((int)rl & 255)) << ((k & 3) * 8);
        if ((k & 3) == 3) {
            int word = ((e * 8 + (k >> 5)) * 8192 + n * 32 + (k & 31) - 3) >> 2;
            hiw[word] = hb; low[word] = lb;
            hb = lb = 0;
        }
    }
}

// ---------------------------------------------------------------- row quantize
// src [B,256] f32 -> int8 hi/lo planes + per-row scale. Warp per row.
__global__ void quant_rows(const float* __restrict__ src,
                           int8_t* __restrict__ qhi, int8_t* __restrict__ qlo,
                           float* __restrict__ sxout) {
    const int r = blockIdx.x * 8 + (threadIdx.x >> 5);
    const int lane = threadIdx.x & 31;
    const float* p = src + (size_t)r * 256 + lane * 8;
    float4 f0 = *(const float4*)p;
    float4 f1 = *(const float4*)(p + 4);
    float v[8] = {f0.x, f0.y, f0.z, f0.w, f1.x, f1.y, f1.z, f1.w};
    float m = 0.f;
#pragma unroll
    for (int i = 0; i < 8; ++i) m = fmaxf(m, fabsf(v[i]));
#pragma unroll
    for (int o = 16; o > 0; o >>= 1) m = fmaxf(m, __shfl_xor_sync(~0u, m, o));
    const float sx = fmaxf(m, 1e-30f);
    if (lane == 0) sxout[r] = sx;
    const float qsc = 127.0f / sx;
    uint32_t hw[2] = {0, 0}, lw[2] = {0, 0};
#pragma unroll
    for (int i = 0; i < 8; ++i) {
        float qf = v[i] * qsc;
        float h  = rintf(qf);
        float rl = fminf(rintf((qf - h) * 256.0f), 127.0f);
        hw[i >> 2] |= ((uint32_t)((int)h  & 255)) << ((i & 3) * 8);
        lw[i >> 2] |= ((uint32_t)((int)rl & 255)) << ((i & 3) * 8);
    }
    *(uint2*)(qhi + (size_t)r * 256 + lane * 8) = make_uint2(hw[0], hw[1]);
    *(uint2*)(qlo + (size_t)r * 256 + lane * 8) = make_uint2(lw[0], lw[1]);
}

// ---------------------------------------------------------------- layer (IMMA)
// Tile 64 rows x 128 cols, 2048 CTAs, 512 threads = 4 M-warps x 4 N-warps.
template <bool RELU>
__global__ void __launch_bounds__(512, 1) layer_imma(
    const int8_t* __restrict__ Ahi, const int8_t* __restrict__ Alo,
    const int8_t* __restrict__ W8hi, const int8_t* __restrict__ W8lo,
    const float* __restrict__ sx, const float* __restrict__ sweP,
    const float* __restrict__ bias, float* __restrict__ Out)
{
    extern __shared__ char smem[];
    const uint32_t sb = smem_u32(smem);
    const int tid = threadIdx.x, lane = tid & 31, wid = tid >> 5;
    const int mwarp = wid >> 2, nwarp = wid & 3;   // 4 M x 4 N
    const int rowbase = (blockIdx.x >> 1) << 6;
    const int colbase = (blockIdx.x & 1) << 7;

    // ---- A tile 64x256 int8 hi/lo via cp.async (group 0)
#pragma unroll
    for (int u = tid; u < 1024; u += 512) {
        int r = u >> 4, s = u & 15;
        cpa16(sb + r * ASTR8 + s * 16,
              Ahi + (size_t)(rowbase + r) * 256 + s * 16);
        cpa16(sb + SA8_LO + r * ASTR8 + s * 16,
              Alo + (size_t)(rowbase + r) * 256 + s * 16);
    }
    asm volatile("cp.async.commit_group;" ::: "memory");

    // per-thread B chunk cp.async mapping: 512 threads x 16B
    const int bp = tid >> 8;                  // 0 = hi, 1 = lo
    const int bi = tid & 255;
    const int bnn = bi >> 1, bsg = bi & 1;
    const uint32_t bdst = sb + SB8_OFF + bp * SB8_LO + bnn * BSTR8 + bsg * 16;
    const int8_t* bsrcbase = (bp ? W8lo : W8hi);
    const uint32_t bsoff = (uint32_t)(colbase + bnn) * 32 + bsg * 16;

#pragma unroll
    for (int c = 0; c < 3; ++c) {
        cpa16(bdst + c * SB8_STAGE, bsrcbase + (size_t)c * 8192 + bsoff);
        asm volatile("cp.async.commit_group;" ::: "memory");
    }

    // bias -> smem [e][128] this col-half
    ((float*)(smem + SBIAS8))[tid] = bias[(tid >> 7) * NDIM + colbase + (tid & 127)];

    const int gr0 = rowbase + mwarp * 16 + (lane >> 2);
    const float4 cva = g_coeff[gr0];
    const float4 cvb = g_coeff[gr0 + 8];
    const float sxa = sx[gr0] * (1.0f / 16129.0f);
    const float sxb = sx[gr0 + 8] * (1.0f / 16129.0f);
    const float sw0 = sweP[0], sw1 = sweP[1], sw2 = sweP[2], sw3 = sweP[3];

    // ldmatrix lane patterns
    const int arow = (lane & 7) + (((lane >> 3) & 1) << 3);
    const int akh  = lane >> 4;
    const uint32_t aBase = sb + (mwarp * 16 + arow) * ASTR8 + akh * 16;
    const int bcol = (lane & 7) + ((lane >> 4) << 3);
    const int bkh  = (lane >> 3) & 1;
    const uint32_t bBase = sb + SB8_OFF + (nwarp * 32 + bcol) * BSTR8 + bkh * 16;

    int acc[32];
    float outv[16];
#pragma unroll
    for (int i = 0; i < 32; ++i) acc[i] = 0;
#pragma unroll
    for (int i = 0; i < 16; ++i) outv[i] = 0.f;

#pragma unroll
    for (int e = 0; e < 4; ++e) {
#pragma unroll
        for (int kc = 0; kc < 8; ++kc) {
            const int t = e * 8 + kc;
            if (t < 30)      asm volatile("cp.async.wait_group 2;" ::: "memory");
            else if (t == 30) asm volatile("cp.async.wait_group 1;" ::: "memory");
            else              asm volatile("cp.async.wait_group 0;" ::: "memory");
            __syncthreads();
            if (t < 29) {
                cpa16(bdst + ((t + 3) & 3) * SB8_STAGE,
                      bsrcbase + (size_t)(t + 3) * 8192 + bsoff);
                asm volatile("cp.async.commit_group;" ::: "memory");
            }
            uint32_t ah[4], al[4];
            ldsm4(ah, aBase + kc * 32);
            ldsm4(al, aBase + SA8_LO + kc * 32);
            const uint32_t bS = bBase + (t & 3) * SB8_STAGE;
#pragma unroll
            for (int gpp = 0; gpp < 2; ++gpp) {
                uint32_t bh[4], bl[4];
                const uint32_t ba = bS + gpp * (16 * BSTR8);
                ldsm4(bh, ba);
                ldsm4(bl, ba + SB8_LO);
                int* c1a = acc + gpp * 16;      // tile0 hh
                int* c2a = c1a + 4;             // tile0 cross
                int* c1b = c1a + 8;             // tile1 hh
                int* c2b = c1a + 12;            // tile1 cross
                imma16832(c1a, ah, bh[0], bh[1]);
                imma16832(c1b, ah, bh[2], bh[3]);
                imma16832(c2a, ah, bl[0], bl[1]);
                imma16832(c2b, ah, bl[2], bl[3]);
                imma16832(c2a, al, bh[0], bh[1]);
                imma16832(c2b, al, bh[2], bh[3]);
            }
        }
        // fold expert e: outv += ce*sx*swe/16129 * (acc_hh + acc_cross/256)
        const float ce  = (e == 0) ? cva.x : (e == 1) ? cva.y : (e == 2) ? cva.z : cva.w;
        const float ceb = (e == 0) ? cvb.x : (e == 1) ? cvb.y : (e == 2) ? cvb.z : cvb.w;
        const float swe = (e == 0) ? sw0 : (e == 1) ? sw1 : (e == 2) ? sw2 : sw3;
        const float fa = ce  * sxa * swe;
        const float fb = ceb * sxb * swe;
#pragma unroll
        for (int j = 0; j < 4; ++j) {
            const int ab = (j >> 1) * 16 + (j & 1) * 8;
            outv[j * 4 + 0] += fa * ((float)acc[ab + 0] + (float)acc[ab + 4] * 0.00390625f);
            outv[j * 4 + 1] += fa * ((float)acc[ab + 1] + (float)acc[ab + 5] * 0.00390625f);
            outv[j * 4 + 2] += fb * ((float)acc[ab + 2] + (float)acc[ab + 6] * 0.00390625f);
            outv[j * 4 + 3] += fb * ((float)acc[ab + 3] + (float)acc[ab + 7] * 0.00390625f);
#pragma unroll
            for (int q = 0; q < 8; ++q) acc[ab + q] = 0;
        }
    }

    // ---- epilogue: + sum_e c_e*b_e[n], ReLU, f32 store
    const float* bsm = (const float*)(smem + SBIAS8);
#pragma unroll
    for (int j = 0; j < 4; ++j) {
        const int nc = nwarp * 32 + j * 8 + (lane & 3) * 2;
        const int n0 = colbase + nc;
        float b00 = cva.x * bsm[nc] + cva.y * bsm[128 + nc]
                  + cva.z * bsm[256 + nc] + cva.w * bsm[384 + nc];
        float b01 = cva.x * bsm[nc + 1] + cva.y * bsm[128 + nc + 1]
                  + cva.z * bsm[256 + nc + 1] + cva.w * bsm[384 + nc + 1];
        float b10 = cvb.x * bsm[nc] + cvb.y * bsm[128 + nc]
                  + cvb.z * bsm[256 + nc] + cvb.w * bsm[384 + nc];
        float b11 = cvb.x * bsm[nc + 1] + cvb.y * bsm[128 + nc + 1]
                  + cvb.z * bsm[256 + nc + 1] + cvb.w * bsm[384 + nc + 1];
        float v0 = outv[j * 4 + 0] + b00, v1 = outv[j * 4 + 1] + b01;
        float v2 = outv[j * 4 + 2] + b10, v3 = outv[j * 4 + 3] + b11;
        if (RELU) {
            v0 = fmaxf(v0, 0.f); v1 = fmaxf(v1, 0.f);
            v2 = fmaxf(v2, 0.f); v3 = fmaxf(v3, 0.f);
        }
        *(float2*)(Out + (size_t)gr0 * NDIM + n0)       = make_float2(v0, v1);
        *(float2*)(Out + (size_t)(gr0 + 8) * NDIM + n0) = make_float2(v2, v3);
    }
}

// ---------------------------------------------------------------- launch
extern "C" void kernel_launch(void* const* d_in, const int* in_sizes, int n_in,
                              void* d_out, int out_size) {
    const float* X   = (const float*)d_in[0];
    const float* phi = (const float*)d_in[1];
    const float* W1  = (const float*)d_in[2];
    const float* b1  = (const float*)d_in[3];
    const float* W2  = (const float*)d_in[4];
    const float* b2  = (const float*)d_in[5];
    const float* W3  = (const float*)d_in[6];
    const float* b3  = (const float*)d_in[7];
    float* out = (float*)d_out;

    float *H1, *H2, *sxA, *sxB, *swe;
    int8_t *W8hi, *W8lo, *A8hi, *A8lo, *B8hi, *B8lo;
    cudaGetSymbolAddress((void**)&H1, g_H1);
    cudaGetSymbolAddress((void**)&H2, g_H2);
    cudaGetSymbolAddress((void**)&sxA, g_sxA);
    cudaGetSymbolAddress((void**)&sxB, g_sxB);
    cudaGetSymbolAddress((void**)&swe, g_swe);
    cudaGetSymbolAddress((void**)&W8hi, g_W8hi);
    cudaGetSymbolAddress((void**)&W8lo, g_W8lo);
    cudaGetSymbolAddress((void**)&A8hi, g_A8hi);
    cudaGetSymbolAddress((void**)&A8lo, g_A8lo);
    cudaGetSymbolAddress((void**)&B8hi, g_B8hi);
    cudaGetSymbolAddress((void**)&B8lo, g_B8lo);

    cudaFuncSetAttribute(layer_imma<true>,
                         cudaFuncAttributeMaxDynamicSharedMemorySize, SM8_TOTAL);
    cudaFuncSetAttribute(layer_imma<false>,
                         cudaFuncAttributeMaxDynamicSharedMemorySize, SM8_TOTAL);

    coeff_kernel<<<BSZ / 256, 256>>>(phi);               // 0
    convW8_kernel<<<dim3(4, 3), 256>>>(W1, W2, W3);      // 1
    quant_rows<<<BSZ / 8, 256>>>(X, A8hi, A8lo, sxA);    // 2

    // L1: A8 -> H1                                         (3)
    layer_imma<true><<<2048, 512, SM8_TOTAL>>>(
        A8hi, A8lo, W8hi, W8lo, sxA, swe, b1, H1);
    quant_rows<<<BSZ / 8, 256>>>(H1, B8hi, B8lo, sxB);   // 4
    // L2: B8 -> H2                                         (5 — ncu lands here)
    layer_imma<true><<<2048, 512, SM8_TOTAL>>>(
        B8hi, B8lo, W8hi + 262144, W8lo + 262144, sxB, swe + 4, b2, H2);
    quant_rows<<<BSZ / 8, 256>>>(H2, A8hi, A8lo, sxA);   // 6
    // L3: A8 -> out                                        (7)
    layer_imma<false><<<2048, 512, SM8_TOTAL>>>(
        A8hi, A8lo, W8hi + 524288, W8lo + 524288, sxA, swe + 8, b3, out);
}

// round 11
// speedup vs baseline: 2.1598x; 2.1598x over previous
#include <cuda_runtime.h>
#include <cuda_bf16.h>
#include <cstdint>

// MotionPrediction: B=65536, 3 cyclic-MoE layers, dims 256, 4 experts.
// out = sum_e c_e (.) (X @ W_e + b_e), ReLU on layers 1,2.
// HMMA mma.sync m16n8k16 bf16, hi/lo split (3 products) ~ fp32 accuracy.
// R10: 32x32 warp tiles (B-frag reuse over 2 M-tiles), k64 stages with
// 2-stage double buffer (16 barriers), 8 independent accumulators.

#define BSZ  65536
#define NDIM 256

__device__ __align__(16) __nv_bfloat16 g_Whi[3 * 4 * NDIM * NDIM]; // [slot][chunk64=e*4+q][n256][k64]
__device__ __align__(16) __nv_bfloat16 g_Wlo[3 * 4 * NDIM * NDIM];
__device__ __align__(16) __nv_bfloat16 g_Ahi[BSZ * NDIM];
__device__ __align__(16) __nv_bfloat16 g_Alo[BSZ * NDIM];
__device__ __align__(16) __nv_bfloat16 g_Bhi[BSZ * NDIM];
__device__ __align__(16) __nv_bfloat16 g_Blo[BSZ * NDIM];
__device__ float4 g_coeff[BSZ];

// ---- SMEM map (bytes) ----
#define ASTR      528                 // A row stride (256 bf16 + pad)
#define SA_LO     67584               // A_lo = A_hi + 128*528
#define SB_OFF    135168              // 2 B stages (k64)
#define BSTR2     144                 // B row stride (64 bf16 + pad)
#define SB2_LO    18432               // 128*144
#define SB2_STAGE 36864               // hi+lo
#define SBIAS     208896              // 512 floats
#define SM_TOTAL  210944

// ---------------------------------------------------------------- helpers
__device__ __forceinline__ uint32_t smem_u32(const void* p) {
    uint32_t a;
    asm("{ .reg .u64 t; cvta.to.shared.u64 t, %1; cvt.u32.u64 %0, t; }"
        : "=r"(a) : "l"(p));
    return a;
}
__device__ __forceinline__ void ldsm4(uint32_t* r, uint32_t a) {
    asm volatile("ldmatrix.sync.aligned.m8n8.x4.shared.b16 {%0,%1,%2,%3}, [%4];"
                 : "=r"(r[0]), "=r"(r[1]), "=r"(r[2]), "=r"(r[3]) : "r"(a));
}
__device__ __forceinline__ void mma16816(float* d, const uint32_t* a,
                                         uint32_t b0, uint32_t b1) {
    asm volatile(
        "mma.sync.aligned.m16n8k16.row.col.f32.bf16.bf16.f32 "
        "{%0,%1,%2,%3}, {%4,%5,%6,%7}, {%8,%9}, {%0,%1,%2,%3};"
        : "+f"(d[0]), "+f"(d[1]), "+f"(d[2]), "+f"(d[3])
        : "r"(a[0]), "r"(a[1]), "r"(a[2]), "r"(a[3]), "r"(b0), "r"(b1));
}
__device__ __forceinline__ void cpa16(uint32_t s, const void* g) {
    asm volatile("cp.async.cg.shared.global [%0], [%1], 16;" :: "r"(s), "l"(g));
}
__device__ __forceinline__ void split_bf16(float v, unsigned short& h, unsigned short& l) {
    __nv_bfloat16 hb = __float2bfloat16_rn(v);
    float r = v - __bfloat162float(hb);
    h = __bfloat16_as_ushort(hb);
    l = __bfloat16_as_ushort(__float2bfloat16_rn(r));
}

// ---------------------------------------------------------------- coeff
__global__ void coeff_kernel(const float* __restrict__ phi) {
    int b = blockIdx.x * blockDim.x + threadIdx.x;
    if (b >= BSZ) return;
    const float TWO_OVER_PI = (float)(2.0 / 3.14159265358979323846);
    float w  = TWO_OVER_PI * phi[b];
    int  wi  = ((int)w) & 3;
    float w2 = w * w, w3 = w2 * w;
    float co[4];
    co[0] = -0.5f * w + w2 - 0.5f * w3;
    co[1] = -2.5f * w2 + 1.5f * w3;
    co[2] =  0.5f * w + 2.0f * w2 - 1.5f * w3;
    co[3] = -0.5f * w2 + 0.5f * w3;
    float c[4];
#pragma unroll
    for (int e = 0; e < 4; ++e) c[e] = co[(e - wi + 5) & 3];
    g_coeff[b] = make_float4(c[0], c[1], c[2], c[3]);
}

// ---------------------------------------------------------------- X convert
__global__ void convX_kernel(const float* __restrict__ X) {
    size_t i = ((size_t)blockIdx.x * 256 + threadIdx.x) * 4;
    float4 f = *(const float4*)(X + i);
    float v[4] = {f.x, f.y, f.z, f.w};
    unsigned short h[4], l[4];
#pragma unroll
    for (int p = 0; p < 4; ++p) split_bf16(v[p], h[p], l[p]);
    *(uint2*)(g_Ahi + i) = make_uint2((uint32_t)h[0] | ((uint32_t)h[1] << 16),
                                      (uint32_t)h[2] | ((uint32_t)h[3] << 16));
    *(uint2*)(g_Alo + i) = make_uint2((uint32_t)l[0] | ((uint32_t)l[1] << 16),
                                      (uint32_t)l[2] | ((uint32_t)l[3] << 16));
}

// ---------------------------------------------------------------- W convert
// W [4][256 k][256 n] f32 -> blocked [chunk64=e*4+q][n 256][k 64] bf16 hi/lo
__global__ void convW3_kernel(const float* __restrict__ Wa,
                              const float* __restrict__ Wb,
                              const float* __restrict__ Wc) {
    int i = blockIdx.x * 256 + threadIdx.x;     // 262144 per layer
    int slot = blockIdx.y;
    const float* W = (slot == 0) ? Wa : (slot == 1) ? Wb : Wc;
    int c = i >> 14;             // chunk64
    int n = (i >> 6) & 255;
    int k = i & 63;
    int e = c >> 2, q = c & 3;
    float w = W[(e * 256 + q * 64 + k) * NDIM + n];
    unsigned short h, l;
    split_bf16(w, h, l);
    g_Whi[(size_t)slot * 262144 + i] = __ushort_as_bfloat16(h);
    g_Wlo[(size_t)slot * 262144 + i] = __ushort_as_bfloat16(l);
}

// ---------------------------------------------------------------- layer
template <bool RELU, bool BF16OUT>
__global__ void __launch_bounds__(512, 1) layer_hmma(
    const __nv_bfloat16* __restrict__ Xhi,
    const __nv_bfloat16* __restrict__ Xlo,
    const __nv_bfloat16* __restrict__ Whi,
    const __nv_bfloat16* __restrict__ Wlo,
    const float* __restrict__ bias,
    __nv_bfloat16* __restrict__ Ohi,
    __nv_bfloat16* __restrict__ Olo,
    float* __restrict__ Out)
{
    extern __shared__ char smem[];
    const uint32_t sb = smem_u32(smem);
    const int tid = threadIdx.x, lane = tid & 31, wid = tid >> 5;
    const int mwarp = wid >> 2, nwarp = wid & 3;   // 4 M-warps x 4 N-warps
    const int mtile = blockIdx.x >> 1, ch = blockIdx.x & 1;
    const int rowbase = mtile << 7, colbase = ch << 7;

    // A tile: 128 rows x 256 bf16 hi/lo via cp.async (group 0)
#pragma unroll
    for (int u = tid; u < 4096; u += 512) {
        int r = u >> 5, s = u & 31;
        cpa16(sb + r * ASTR + s * 16,         Xhi + (size_t)(rowbase + r) * NDIM + s * 16 / 2);
        cpa16(sb + SA_LO + r * ASTR + s * 16, Xlo + (size_t)(rowbase + r) * NDIM + s * 16 / 2);
    }
    asm volatile("cp.async.commit_group;" ::: "memory");

    // per-thread B stage cp.async mapping: plane p, row n, 4 quads
    const int bp = tid >> 8;                  // 0 = hi, 1 = lo
    const int br = tid & 255;
    const int bn = br >> 1, bh2 = br & 1;
    const uint32_t bdst0 = sb + SB_OFF + bp * SB2_LO + bn * BSTR2 + bh2 * 64;
    const char* bsrcbase = (const char*)(bp ? Wlo : Whi);
    const uint32_t bsoff = (uint32_t)(colbase + bn) * 128 + bh2 * 64;

    // preload stage 0 (chunk 0)
#pragma unroll
    for (int j = 0; j < 4; ++j)
        cpa16(bdst0 + j * 16, bsrcbase + bsoff + j * 16);
    asm volatile("cp.async.commit_group;" ::: "memory");

    // bias -> smem: [e][128] for this col half
    ((float*)(smem + SBIAS))[tid] = bias[(tid >> 7) * NDIM + colbase + (tid & 127)];

    const int gr0 = rowbase + mwarp * 32 + (lane >> 2);

    const int lrow = (lane & 7) + (((lane >> 3) & 1) << 3);
    const int lkof = (lane >> 4) << 3;
    const uint32_t aB0 = sb + (mwarp * 32 + lrow) * ASTR + lkof * 2;
    const uint32_t aB1 = aB0 + 16 * ASTR;
    const uint32_t bBase = sb + SB_OFF + (nwarp * 32 + lrow) * BSTR2 + lkof * 2;

    float acc[32], outv[32];
#pragma unroll
    for (int i = 0; i < 32; ++i) { acc[i] = 0.f; outv[i] = 0.f; }

#pragma unroll
    for (int e = 0; e < 4; ++e) {
#pragma unroll
        for (int q = 0; q < 4; ++q) {
            const int t = e * 4 + q;
            asm volatile("cp.async.wait_group 0;" ::: "memory");
            __syncthreads();
            if (t < 15) {   // prefetch chunk t+1 into stage (t+1)&1
                const uint32_t d = bdst0 + ((t + 1) & 1) * SB2_STAGE;
                const char* s = bsrcbase + ((size_t)(t + 1) << 15) + bsoff;
#pragma unroll
                for (int j = 0; j < 4; ++j) cpa16(d + j * 16, s + j * 16);
                asm volatile("cp.async.commit_group;" ::: "memory");
            }
            const uint32_t bS = bBase + (t & 1) * SB2_STAGE;
#pragma unroll
            for (int kc2 = 0; kc2 < 2; ++kc2) {
#pragma unroll
                for (int ks = 0; ks < 2; ++ks) {
                    const int kb = kc2 * 32 + ks * 16;       // k within stage
                    const int kg = q * 64 + kb;              // k within A row
                    uint32_t ah0[4], ah1[4], al0[4], al1[4];
                    ldsm4(ah0, aB0 + kg * 2);
                    ldsm4(ah1, aB1 + kg * 2);
                    ldsm4(al0, aB0 + SA_LO + kg * 2);
                    ldsm4(al1, aB1 + SA_LO + kg * 2);
                    uint32_t bh0[4], bh1[4], bl0[4], bl1[4];
                    ldsm4(bh0, bS + kb * 2);
                    ldsm4(bh1, bS + 16 * BSTR2 + kb * 2);
                    ldsm4(bl0, bS + SB2_LO + kb * 2);
                    ldsm4(bl1, bS + SB2_LO + 16 * BSTR2 + kb * 2);
                    float* c00 = acc;      float* c01 = acc + 4;
                    float* c02 = acc + 8;  float* c03 = acc + 12;
                    float* c10 = acc + 16; float* c11 = acc + 20;
                    float* c12 = acc + 24; float* c13 = acc + 28;
                    // hh (8 independent)
                    mma16816(c00, ah0, bh0[0], bh0[2]);
                    mma16816(c10, ah1, bh0[0], bh0[2]);
                    mma16816(c01, ah0, bh0[1], bh0[3]);
                    mma16816(c11, ah1, bh0[1], bh0[3]);
                    mma16816(c02, ah0, bh1[0], bh1[2]);
                    mma16816(c12, ah1, bh1[0], bh1[2]);
                    mma16816(c03, ah0, bh1[1], bh1[3]);
                    mma16816(c13, ah1, bh1[1], bh1[3]);
                    // lo_A * hi_B
                    mma16816(c00, al0, bh0[0], bh0[2]);
                    mma16816(c10, al1, bh0[0], bh0[2]);
                    mma16816(c01, al0, bh0[1], bh0[3]);
                    mma16816(c11, al1, bh0[1], bh0[3]);
                    mma16816(c02, al0, bh1[0], bh1[2]);
                    mma16816(c12, al1, bh1[0], bh1[2]);
                    mma16816(c03, al0, bh1[1], bh1[3]);
                    mma16816(c13, al1, bh1[1], bh1[3]);
                    // hi_A * lo_B
                    mma16816(c00, ah0, bl0[0], bl0[2]);
                    mma16816(c10, ah1, bl0[0], bl0[2]);
                    mma16816(c01, ah0, bl0[1], bl0[3]);
                    mma16816(c11, ah1, bl0[1], bl0[3]);
                    mma16816(c02, ah0, bl1[0], bl1[2]);
                    mma16816(c12, ah1, bl1[0], bl1[2]);
                    mma16816(c03, ah0, bl1[1], bl1[3]);
                    mma16816(c13, ah1, bl1[1], bl1[3]);
                }
            }
        }
        // fold expert e with per-row coefficients
        {
            const float4 ca = g_coeff[gr0];
            const float4 cb = g_coeff[gr0 + 8];
            const float4 cc = g_coeff[gr0 + 16];
            const float4 cd = g_coeff[gr0 + 24];
            const float f0 = (e == 0) ? ca.x : (e == 1) ? ca.y : (e == 2) ? ca.z : ca.w;
            const float f1 = (e == 0) ? cb.x : (e == 1) ? cb.y : (e == 2) ? cb.z : cb.w;
            const float f2 = (e == 0) ? cc.x : (e == 1) ? cc.y : (e == 2) ? cc.z : cc.w;
            const float f3 = (e == 0) ? cd.x : (e == 1) ? cd.y : (e == 2) ? cd.z : cd.w;
#pragma unroll
            for (int nt = 0; nt < 4; ++nt) {
                outv[nt * 4 + 0] += f0 * acc[nt * 4 + 0]; acc[nt * 4 + 0] = 0.f;
                outv[nt * 4 + 1] += f0 * acc[nt * 4 + 1]; acc[nt * 4 + 1] = 0.f;
                outv[nt * 4 + 2] += f1 * acc[nt * 4 + 2]; acc[nt * 4 + 2] = 0.f;
                outv[nt * 4 + 3] += f1 * acc[nt * 4 + 3]; acc[nt * 4 + 3] = 0.f;
                outv[16 + nt * 4 + 0] += f2 * acc[16 + nt * 4 + 0]; acc[16 + nt * 4 + 0] = 0.f;
                outv[16 + nt * 4 + 1] += f2 * acc[16 + nt * 4 + 1]; acc[16 + nt * 4 + 1] = 0.f;
                outv[16 + nt * 4 + 2] += f3 * acc[16 + nt * 4 + 2]; acc[16 + nt * 4 + 2] = 0.f;
                outv[16 + nt * 4 + 3] += f3 * acc[16 + nt * 4 + 3]; acc[16 + nt * 4 + 3] = 0.f;
            }
        }
    }

    // ---- epilogue: + sum_e c_e * b_e[n], ReLU, store (f32 or bf16 hi/lo)
    const float* bsm = (const float*)(smem + SBIAS);
#pragma unroll
    for (int mt = 0; mt < 2; ++mt) {
        const int r0 = gr0 + mt * 16, r1 = r0 + 8;
        const float4 ca = g_coeff[r0];
        const float4 cb = g_coeff[r1];
#pragma unroll
        for (int nt = 0; nt < 4; ++nt) {
            const int nc = nwarp * 32 + nt * 8 + (lane & 3) * 2;
            const int n0 = colbase + nc;
            float b00 = ca.x * bsm[nc] + ca.y * bsm[128 + nc]
                      + ca.z * bsm[256 + nc] + ca.w * bsm[384 + nc];
            float b01 = ca.x * bsm[nc + 1] + ca.y * bsm[128 + nc + 1]
                      + ca.z * bsm[256 + nc + 1] + ca.w * bsm[384 + nc + 1];
            float b10 = cb.x * bsm[nc] + cb.y * bsm[128 + nc]
                      + cb.z * bsm[256 + nc] + cb.w * bsm[384 + nc];
            float b11 = cb.x * bsm[nc + 1] + cb.y * bsm[128 + nc + 1]
                      + cb.z * bsm[256 + nc + 1] + cb.w * bsm[384 + nc + 1];
            const float* o = outv + mt * 16 + nt * 4;
            float v0 = o[0] + b00, v1 = o[1] + b01;
            float v2 = o[2] + b10, v3 = o[3] + b11;
            if (RELU) {
                v0 = fmaxf(v0, 0.f); v1 = fmaxf(v1, 0.f);
                v2 = fmaxf(v2, 0.f); v3 = fmaxf(v3, 0.f);
            }
            if (BF16OUT) {
                unsigned short h0, l0, h1, l1, h2, l2, h3, l3;
                split_bf16(v0, h0, l0); split_bf16(v1, h1, l1);
                split_bf16(v2, h2, l2); split_bf16(v3, h3, l3);
                size_t p0 = (size_t)r0 * NDIM + n0;
                size_t p1 = (size_t)r1 * NDIM + n0;
                *(uint32_t*)(Ohi + p0) = (uint32_t)h0 | ((uint32_t)h1 << 16);
                *(uint32_t*)(Olo + p0) = (uint32_t)l0 | ((uint32_t)l1 << 16);
                *(uint32_t*)(Ohi + p1) = (uint32_t)h2 | ((uint32_t)h3 << 16);
                *(uint32_t*)(Olo + p1) = (uint32_t)l2 | ((uint32_t)l3 << 16);
            } else {
                *(float2*)(Out + (size_t)r0 * NDIM + n0) = make_float2(v0, v1);
                *(float2*)(Out + (size_t)r1 * NDIM + n0) = make_float2(v2, v3);
            }
        }
    }
}

// ---------------------------------------------------------------- launch
extern "C" void kernel_launch(void* const* d_in, const int* in_sizes, int n_in,
                              void* d_out, int out_size) {
    const float* X   = (const float*)d_in[0];
    const float* phi = (const float*)d_in[1];
    const float* W1  = (const float*)d_in[2];
    const float* b1  = (const float*)d_in[3];
    const float* W2  = (const float*)d_in[4];
    const float* b2  = (const float*)d_in[5];
    const float* W3  = (const float*)d_in[6];
    const float* b3  = (const float*)d_in[7];
    float* out = (float*)d_out;

    __nv_bfloat16 *Whi, *Wlo, *Ahi, *Alo, *Bhi, *Blo;
    cudaGetSymbolAddress((void**)&Whi, g_Whi);
    cudaGetSymbolAddress((void**)&Wlo, g_Wlo);
    cudaGetSymbolAddress((void**)&Ahi, g_Ahi);
    cudaGetSymbolAddress((void**)&Alo, g_Alo);
    cudaGetSymbolAddress((void**)&Bhi, g_Bhi);
    cudaGetSymbolAddress((void**)&Blo, g_Blo);

    cudaFuncSetAttribute(layer_hmma<true, true>,
                         cudaFuncAttributeMaxDynamicSharedMemorySize, SM_TOTAL);
    cudaFuncSetAttribute(layer_hmma<false, false>,
                         cudaFuncAttributeMaxDynamicSharedMemorySize, SM_TOTAL);

    coeff_kernel<<<BSZ / 256, 256>>>(phi);                 // launch 0
    convX_kernel<<<BSZ * NDIM / 1024, 256>>>(X);           // launch 1
    convW3_kernel<<<dim3(1024, 3), 256>>>(W1, W2, W3);     // launch 2

    // L1: A -> B   (launch 3)
    layer_hmma<true, true><<<1024, 512, SM_TOTAL>>>(
        Ahi, Alo, Whi, Wlo, b1, Bhi, Blo, nullptr);
    // L2: B -> A   (launch 4)
    layer_hmma<true, true><<<1024, 512, SM_TOTAL>>>(
        Bhi, Blo, Whi + 262144, Wlo + 262144, b2, Ahi, Alo, nullptr);
    // L3: A -> out (launch 5)
    layer_hmma<false, false><<<1024, 512, SM_TOTAL>>>(
        Ahi, Alo, Whi + 524288, Wlo + 524288, b3, nullptr, nullptr, out);
}

// round 13
// speedup vs baseline: 2.2402x; 1.0372x over previous
#include <cuda_runtime.h>
#include <cuda_bf16.h>
#include <cstdint>

// MotionPrediction: B=65536, 3 cyclic-MoE layers, dims 256, 4 experts.
// out = sum_e c_e (.) (X @ W_e + b_e), ReLU on layers 1,2.
// HMMA mma.sync m16n8k16 bf16, hi/lo split (3 products) ~ fp32 accuracy.
// R11: 64x128 CTA tile, 256 threads (8 warps = 4Mx2N, warp tile 16x64 as R7),
// smem 108 KB -> 2 CTAs/SM for cross-CTA latency hiding. 2-stage B pipeline.

#define BSZ  65536
#define NDIM 256

__device__ __align__(16) __nv_bfloat16 g_Whi[3 * 4 * NDIM * NDIM]; // [slot][chunk=e*8+kc][n256][k32]
__device__ __align__(16) __nv_bfloat16 g_Wlo[3 * 4 * NDIM * NDIM];
__device__ __align__(16) __nv_bfloat16 g_Ahi[BSZ * NDIM];
__device__ __align__(16) __nv_bfloat16 g_Alo[BSZ * NDIM];
__device__ __align__(16) __nv_bfloat16 g_Bhi[BSZ * NDIM];
__device__ __align__(16) __nv_bfloat16 g_Blo[BSZ * NDIM];
__device__ float4 g_coeff[BSZ];

// ---- SMEM map (bytes) ----
#define ASTR     528                    // A row stride (256 bf16 + pad)
#define SA_LO    33792                  // 64*528
#define SB_OFF   67584                  // 2 B stages
#define SB_STAGE 20480                  // per stage: hi 10240 + lo 10240
#define SB_LO    10240
#define BSTR     80                     // B row stride (32 bf16 + pad)
#define SBIAS    108544                 // 512 floats
#define SM_TOTAL 110592

// ---------------------------------------------------------------- helpers
__device__ __forceinline__ uint32_t smem_u32(const void* p) {
    uint32_t a;
    asm("{ .reg .u64 t; cvta.to.shared.u64 t, %1; cvt.u32.u64 %0, t; }"
        : "=r"(a) : "l"(p));
    return a;
}
__device__ __forceinline__ void ldsm4(uint32_t* r, uint32_t a) {
    asm volatile("ldmatrix.sync.aligned.m8n8.x4.shared.b16 {%0,%1,%2,%3}, [%4];"
                 : "=r"(r[0]), "=r"(r[1]), "=r"(r[2]), "=r"(r[3]) : "r"(a));
}
__device__ __forceinline__ void mma16816(float* d, const uint32_t* a,
                                         uint32_t b0, uint32_t b1) {
    asm volatile(
        "mma.sync.aligned.m16n8k16.row.col.f32.bf16.bf16.f32 "
        "{%0,%1,%2,%3}, {%4,%5,%6,%7}, {%8,%9}, {%0,%1,%2,%3};"
        : "+f"(d[0]), "+f"(d[1]), "+f"(d[2]), "+f"(d[3])
        : "r"(a[0]), "r"(a[1]), "r"(a[2]), "r"(a[3]), "r"(b0), "r"(b1));
}
__device__ __forceinline__ void cpa16(uint32_t s, const void* g) {
    asm volatile("cp.async.cg.shared.global [%0], [%1], 16;" :: "r"(s), "l"(g));
}
__device__ __forceinline__ void split_bf16(float v, unsigned short& h, unsigned short& l) {
    __nv_bfloat16 hb = __float2bfloat16_rn(v);
    float r = v - __bfloat162float(hb);
    h = __bfloat16_as_ushort(hb);
    l = __bfloat16_as_ushort(__float2bfloat16_rn(r));
}

// ---------------------------------------------------------------- coeff
__global__ void coeff_kernel(const float* __restrict__ phi) {
    int b = blockIdx.x * blockDim.x + threadIdx.x;
    if (b >= BSZ) return;
    const float TWO_OVER_PI = (float)(2.0 / 3.14159265358979323846);
    float w  = TWO_OVER_PI * phi[b];
    int  wi  = ((int)w) & 3;
    float w2 = w * w, w3 = w2 * w;
    float co[4];
    co[0] = -0.5f * w + w2 - 0.5f * w3;
    co[1] = -2.5f * w2 + 1.5f * w3;
    co[2] =  0.5f * w + 2.0f * w2 - 1.5f * w3;
    co[3] = -0.5f * w2 + 0.5f * w3;
    float c[4];
#pragma unroll
    for (int e = 0; e < 4; ++e) c[e] = co[(e - wi + 5) & 3];
    g_coeff[b] = make_float4(c[0], c[1], c[2], c[3]);
}

// ---------------------------------------------------------------- X convert
__global__ void convX_kernel(const float* __restrict__ X) {
    size_t i = ((size_t)blockIdx.x * 256 + threadIdx.x) * 4;
    float4 f = *(const float4*)(X + i);
    float v[4] = {f.x, f.y, f.z, f.w};
    unsigned short h[4], l[4];
#pragma unroll
    for (int p = 0; p < 4; ++p) split_bf16(v[p], h[p], l[p]);
    *(uint2*)(g_Ahi + i) = make_uint2((uint32_t)h[0] | ((uint32_t)h[1] << 16),
                                      (uint32_t)h[2] | ((uint32_t)h[3] << 16));
    *(uint2*)(g_Alo + i) = make_uint2((uint32_t)l[0] | ((uint32_t)l[1] << 16),
                                      (uint32_t)l[2] | ((uint32_t)l[3] << 16));
}

// ---------------------------------------------------------------- W convert
// W [4][256 k][256 n] f32 -> blocked [chunk=e*8+kc][n 256][k 32] bf16 hi/lo
__global__ void convW3_kernel(const float* __restrict__ Wa,
                              const float* __restrict__ Wb,
                              const float* __restrict__ Wc) {
    int i = blockIdx.x * 256 + threadIdx.x;     // 262144 per layer
    int slot = blockIdx.y;
    const float* W = (slot == 0) ? Wa : (slot == 1) ? Wb : Wc;
    int chunk = i >> 13;
    int n = (i >> 5) & 255;
    int k = i & 31;
    int e = chunk >> 3, kc = chunk & 7;
    float w = W[((e << 8) + kc * 32 + k) * NDIM + n];
    unsigned short h, l;
    split_bf16(w, h, l);
    g_Whi[(size_t)slot * 262144 + i] = __ushort_as_bfloat16(h);
    g_Wlo[(size_t)slot * 262144 + i] = __ushort_as_bfloat16(l);
}

// ---------------------------------------------------------------- B chunk load
// 256 threads: each thread covers row n = tid>>1, 2 quads of hi + 2 of lo.
__device__ __forceinline__ void load_chunkB(uint32_t sb,
                                            const __nv_bfloat16* __restrict__ Whi,
                                            const __nv_bfloat16* __restrict__ Wlo,
                                            int chunk, int stage, int colbase, int tid) {
    const int n = tid >> 1, qh = (tid & 1) * 2;
    const uint32_t dst = sb + SB_OFF + stage * SB_STAGE + n * BSTR + qh * 16;
    const __nv_bfloat16* sH = Whi + (size_t)chunk * 8192 + (size_t)(colbase + n) * 32 + qh * 8;
    const __nv_bfloat16* sL = Wlo + (size_t)chunk * 8192 + (size_t)(colbase + n) * 32 + qh * 8;
    cpa16(dst,              sH);
    cpa16(dst + 16,         sH + 8);
    cpa16(dst + SB_LO,      sL);
    cpa16(dst + SB_LO + 16, sL + 8);
}

// ---------------------------------------------------------------- layer
template <bool RELU, bool BF16OUT>
__global__ void __launch_bounds__(256, 2) layer_hmma(
    const __nv_bfloat16* __restrict__ Xhi,
    const __nv_bfloat16* __restrict__ Xlo,
    const __nv_bfloat16* __restrict__ Whi,
    const __nv_bfloat16* __restrict__ Wlo,
    const float* __restrict__ bias,
    __nv_bfloat16* __restrict__ Ohi,
    __nv_bfloat16* __restrict__ Olo,
    float* __restrict__ Out)
{
    extern __shared__ char smem[];
    const uint32_t sb = smem_u32(smem);
    const int tid = threadIdx.x, lane = tid & 31, wid = tid >> 5;
    const int mwarp = wid >> 1, nwarp = wid & 1;   // 4 M-warps x 2 N-warps
    const int rowbase = (blockIdx.x >> 1) << 6;    // 64-row tile
    const int colbase = (blockIdx.x & 1) << 7;     // 128-col half

    // A tile: 64 rows x 256 bf16 hi/lo via cp.async (group 0)
#pragma unroll
    for (int u = tid; u < 2048; u += 256) {
        int r = u >> 5, s = u & 31;
        cpa16(sb + r * ASTR + s * 16,         Xhi + (size_t)(rowbase + r) * NDIM + s * 8);
        cpa16(sb + SA_LO + r * ASTR + s * 16, Xlo + (size_t)(rowbase + r) * NDIM + s * 8);
    }
    asm volatile("cp.async.commit_group;" ::: "memory");
    load_chunkB(sb, Whi, Wlo, 0, 0, colbase, tid);
    asm volatile("cp.async.commit_group;" ::: "memory");

    // bias -> smem: [e][128] for this col half (512 floats, 2 per thread)
    {
        float* bsm = (float*)(smem + SBIAS);
        bsm[tid]       = bias[(tid >> 7) * NDIM + colbase + (tid & 127)];
        int i2 = tid + 256;
        bsm[i2]        = bias[(i2 >> 7) * NDIM + colbase + (i2 & 127)];
    }

    const int gr0 = rowbase + mwarp * 16 + (lane >> 2);
    const float4 cva = g_coeff[gr0];
    const float4 cvb = g_coeff[gr0 + 8];

    const int lrow = (lane & 7) + (((lane >> 3) & 1) << 3);
    const int lkof = (lane >> 4) << 3;
    const uint32_t aBase = sb + (mwarp * 16 + lrow) * ASTR + lkof * 2;
    const uint32_t bRow  = sb + SB_OFF + nwarp * (64 * BSTR) + lrow * BSTR + lkof * 2;

    float acc[32], outv[32];
#pragma unroll
    for (int i = 0; i < 32; ++i) { acc[i] = 0.f; outv[i] = 0.f; }

#pragma unroll
    for (int e = 0; e < 4; ++e) {
#pragma unroll
        for (int kc = 0; kc < 8; ++kc) {
            const int t = e * 8 + kc;        // compile-time in unrolled body
            asm volatile("cp.async.wait_group 0;" ::: "memory");
            __syncthreads();
            if (t < 31) {                    // prefetch t+1 into other stage
                load_chunkB(sb, Whi, Wlo, t + 1, (t + 1) & 1, colbase, tid);
                asm volatile("cp.async.commit_group;" ::: "memory");
            }
            const uint32_t bS = bRow + (t & 1) * SB_STAGE;
#pragma unroll
            for (int ks = 0; ks < 2; ++ks) {
                uint32_t ah[4], al[4];
                const uint32_t ak = aBase + (kc * 32 + ks * 16) * 2;
                ldsm4(ah, ak);
                ldsm4(al, ak + SA_LO);
#pragma unroll
                for (int gpp = 0; gpp < 2; ++gpp) {
                    // two 16-col groups -> 4 independent acc tiles in flight
                    uint32_t bha[4], bla[4], bhb[4], blb[4];
                    const uint32_t ba = bS + gpp * (32 * BSTR) + ks * 32;
                    ldsm4(bha, ba);
                    ldsm4(bhb, ba + 16 * BSTR);
                    ldsm4(bla, ba + SB_LO);
                    ldsm4(blb, ba + SB_LO + 16 * BSTR);
                    float* A0 = acc + gpp * 16;
                    float* A1 = A0 + 4;
                    float* A2 = A0 + 8;
                    float* A3 = A0 + 12;
                    mma16816(A0, ah, bha[0], bha[2]);
                    mma16816(A1, ah, bha[1], bha[3]);
                    mma16816(A2, ah, bhb[0], bhb[2]);
                    mma16816(A3, ah, bhb[1], bhb[3]);
                    mma16816(A0, al, bha[0], bha[2]);
                    mma16816(A1, al, bha[1], bha[3]);
                    mma16816(A2, al, bhb[0], bhb[2]);
                    mma16816(A3, al, bhb[1], bhb[3]);
                    mma16816(A0, ah, bla[0], bla[2]);
                    mma16816(A1, ah, bla[1], bla[3]);
                    mma16816(A2, ah, blb[0], blb[2]);
                    mma16816(A3, ah, blb[1], blb[3]);
                }
            }
        }
        const float ce0 = (e == 0) ? cva.x : (e == 1) ? cva.y : (e == 2) ? cva.z : cva.w;
        const float ce1 = (e == 0) ? cvb.x : (e == 1) ? cvb.y : (e == 2) ? cvb.z : cvb.w;
#pragma unroll
        for (int i = 0; i < 32; i += 4) {
            outv[i]     += ce0 * acc[i];     acc[i]     = 0.f;
            outv[i + 1] += ce0 * acc[i + 1]; acc[i + 1] = 0.f;
            outv[i + 2] += ce1 * acc[i + 2]; acc[i + 2] = 0.f;
            outv[i + 3] += ce1 * acc[i + 3]; acc[i + 3] = 0.f;
        }
    }

    // ---- epilogue: + sum_e c_e * b_e[n], ReLU, store (f32 or bf16 hi/lo)
    const float* bsm = (const float*)(smem + SBIAS);
#pragma unroll
    for (int j = 0; j < 8; ++j) {            // 8 n8-tiles, acc base j*4
        const int nc = nwarp * 64 + j * 8 + (lane & 3) * 2;   // col within half
        const int n0 = colbase + nc;
        float b00 = cva.x * bsm[nc] + cva.y * bsm[128 + nc]
                  + cva.z * bsm[256 + nc] + cva.w * bsm[384 + nc];
        float b01 = cva.x * bsm[nc + 1] + cva.y * bsm[128 + nc + 1]
                  + cva.z * bsm[256 + nc + 1] + cva.w * bsm[384 + nc + 1];
        float b10 = cvb.x * bsm[nc] + cvb.y * bsm[128 + nc]
                  + cvb.z * bsm[256 + nc] + cvb.w * bsm[384 + nc];
        float b11 = cvb.x * bsm[nc + 1] + cvb.y * bsm[128 + nc + 1]
                  + cvb.z * bsm[256 + nc + 1] + cvb.w * bsm[384 + nc + 1];
        const float* o = outv + j * 4;
        float v0 = o[0] + b00, v1 = o[1] + b01;
        float v2 = o[2] + b10, v3 = o[3] + b11;
        if (RELU) {
            v0 = fmaxf(v0, 0.f); v1 = fmaxf(v1, 0.f);
            v2 = fmaxf(v2, 0.f); v3 = fmaxf(v3, 0.f);
        }
        if (BF16OUT) {
            unsigned short h0, l0, h1, l1, h2, l2, h3, l3;
            split_bf16(v0, h0, l0); split_bf16(v1, h1, l1);
            split_bf16(v2, h2, l2); split_bf16(v3, h3, l3);
            size_t p0 = (size_t)gr0 * NDIM + n0;
            size_t p1 = (size_t)(gr0 + 8) * NDIM + n0;
            *(uint32_t*)(Ohi + p0) = (uint32_t)h0 | ((uint32_t)h1 << 16);
            *(uint32_t*)(Olo + p0) = (uint32_t)l0 | ((uint32_t)l1 << 16);
            *(uint32_t*)(Ohi + p1) = (uint32_t)h2 | ((uint32_t)h3 << 16);
            *(uint32_t*)(Olo + p1) = (uint32_t)l2 | ((uint32_t)l3 << 16);
        } else {
            *(float2*)(Out + (size_t)gr0 * NDIM + n0)       = make_float2(v0, v1);
            *(float2*)(Out + (size_t)(gr0 + 8) * NDIM + n0) = make_float2(v2, v3);
        }
    }
}

// ---------------------------------------------------------------- launch
extern "C" void kernel_launch(void* const* d_in, const int* in_sizes, int n_in,
                              void* d_out, int out_size) {
    const float* X   = (const float*)d_in[0];
    const float* phi = (const float*)d_in[1];
    const float* W1  = (const float*)d_in[2];
    const float* b1  = (const float*)d_in[3];
    const float* W2  = (const float*)d_in[4];
    const float* b2  = (const float*)d_in[5];
    const float* W3  = (const float*)d_in[6];
    const float* b3  = (const float*)d_in[7];
    float* out = (float*)d_out;

    __nv_bfloat16 *Whi, *Wlo, *Ahi, *Alo, *Bhi, *Blo;
    cudaGetSymbolAddress((void**)&Whi, g_Whi);
    cudaGetSymbolAddress((void**)&Wlo, g_Wlo);
    cudaGetSymbolAddress((void**)&Ahi, g_Ahi);
    cudaGetSymbolAddress((void**)&Alo, g_Alo);
    cudaGetSymbolAddress((void**)&Bhi, g_Bhi);
    cudaGetSymbolAddress((void**)&Blo, g_Blo);

    cudaFuncSetAttribute(layer_hmma<true, true>,
                         cudaFuncAttributeMaxDynamicSharedMemorySize, SM_TOTAL);
    cudaFuncSetAttribute(layer_hmma<false, false>,
                         cudaFuncAttributeMaxDynamicSharedMemorySize, SM_TOTAL);

    coeff_kernel<<<BSZ / 256, 256>>>(phi);                 // launch 0
    convX_kernel<<<BSZ * NDIM / 1024, 256>>>(X);           // launch 1
    convW3_kernel<<<dim3(1024, 3), 256>>>(W1, W2, W3);     // launch 2

    // L1: A -> B   (launch 3)
    layer_hmma<true, true><<<2048, 256, SM_TOTAL>>>(
        Ahi, Alo, Whi, Wlo, b1, Bhi, Blo, nullptr);
    // L2: B -> A   (launch 4)
    layer_hmma<true, true><<<2048, 256, SM_TOTAL>>>(
        Bhi, Blo, Whi + 262144, Wlo + 262144, b2, Ahi, Alo, nullptr);
    // L3: A -> out (launch 5)
    layer_hmma<false, false><<<2048, 256, SM_TOTAL>>>(
        Ahi, Alo, Whi + 524288, Wlo + 524288, b3, nullptr, nullptr, out);
}